// round 6
// baseline (speedup 1.0000x reference)
#include <cuda_runtime.h>
#include <cuda_fp16.h>
#include <cstdint>

// ---------------- problem constants ----------------
#define N_TOK   16384          // B*S
#define D_DIM   256
#define K_SUB   3686
#define K_PAD   3840           // 15 * 256
#define N_YT    15             // candidate tiles of 256
#define K_STORE 512            // stored K: [hi|lo]
#define OUT_TOKENS  (N_TOK * D_DIM)
#define OUT_LOSS    OUT_TOKENS
#define OUT_IDX     (OUT_TOKENS + 1)

// ---------------- device scratch ----------------
__device__ __align__(16) __half g_xb[N_TOK * K_STORE];    // [xh|xl] 16.8 MB
__device__ __align__(16) __half g_cb2[K_PAD * K_STORE];   // [ch|cl]  3.9 MB
__device__ float g_c2[K_PAD];
__device__ unsigned long long g_best64[N_TOK];            // packed (dist,idx)
__device__ int   g_fidx[N_TOK];
__device__ float g_partial[1024];

// ---------------- PTX helpers ----------------
__device__ __forceinline__ uint32_t smem_u32(const void* p) {
    uint32_t a;
    asm("{ .reg .u64 t; cvta.to.shared.u64 t, %1; cvt.u32.u64 %0, t; }" : "=r"(a) : "l"(p));
    return a;
}
__device__ __forceinline__ void cpa16(uint32_t dst, const void* src) {
    asm volatile("cp.async.cg.shared.global [%0], [%1], 16;" :: "r"(dst), "l"(src));
}
#define CP_COMMIT() asm volatile("cp.async.commit_group;" ::: "memory")
#define CP_WAIT(n)  asm volatile("cp.async.wait_group %0;" :: "n"(n) : "memory")

__device__ __forceinline__ void ldsm4(uint32_t* r, uint32_t a) {
    asm volatile("ldmatrix.sync.aligned.m8n8.x4.shared.b16 {%0,%1,%2,%3}, [%4];"
        : "=r"(r[0]), "=r"(r[1]), "=r"(r[2]), "=r"(r[3]) : "r"(a));
}
__device__ __forceinline__ void mma16816(float* c, const uint32_t* a,
                                         uint32_t b0, uint32_t b1) {
    asm volatile("mma.sync.aligned.m16n8k16.row.col.f32.f16.f16.f32 "
        "{%0,%1,%2,%3}, {%4,%5,%6,%7}, {%8,%9}, {%0,%1,%2,%3};"
        : "+f"(c[0]), "+f"(c[1]), "+f"(c[2]), "+f"(c[3])
        : "r"(a[0]), "r"(a[1]), "r"(a[2]), "r"(a[3]), "r"(b0), "r"(b1));
}

// order-preserving float -> uint32 map
__device__ __forceinline__ uint32_t fmap(float f) {
    uint32_t b = __float_as_uint(f);
    return (b & 0x80000000u) ? ~b : (b | 0x80000000u);
}

// ---------------- kernel 1a: split x -> fp16 hi/lo [xh|xl]; init g_best64 ----
__global__ void k_prep_x(const float* __restrict__ x) {
    int i = blockIdx.x * 256 + threadIdx.x;       // float4 index (1M)
    if (i < N_TOK) g_best64[i] = 0xFFFFFFFFFFFFFFFFull;
    int tok = i >> 6, d4 = i & 63;
    float4 v = ((const float4*)x)[i];
    __half hx = __float2half_rn(v.x), hy = __float2half_rn(v.y);
    __half hz = __float2half_rn(v.z), hw = __float2half_rn(v.w);
    __half lx = __float2half_rn(v.x - __half2float(hx));
    __half ly = __float2half_rn(v.y - __half2float(hy));
    __half lz = __float2half_rn(v.z - __half2float(hz));
    __half lw = __float2half_rn(v.w - __half2float(hw));
    __half2* base = (__half2*)(g_xb + (size_t)tok * K_STORE + d4 * 4);
    base[0] = __halves2half2(hx, hy); base[1] = __halves2half2(hz, hw);
    base[128] = __halves2half2(lx, ly); base[129] = __halves2half2(lz, lw);
}

// ---- kernel 1b: gather sub-codebook, split [ch|cl], row norms ----
__global__ void k_prep_c(const float* __restrict__ cb, const int* __restrict__ rnd) {
    int k = blockIdx.x;          // 0..K_PAD-1
    int t = threadIdx.x;         // 64 threads x float4
    __shared__ float ssum[2];
    float4 v = make_float4(0.f, 0.f, 0.f, 0.f);
    if (k < K_SUB) v = ((const float4*)(cb + (size_t)rnd[k] * D_DIM))[t];
    __half hx = __float2half_rn(v.x), hy = __float2half_rn(v.y);
    __half hz = __float2half_rn(v.z), hw = __float2half_rn(v.w);
    __half lx = __float2half_rn(v.x - __half2float(hx));
    __half ly = __float2half_rn(v.y - __half2float(hy));
    __half lz = __float2half_rn(v.z - __half2float(hz));
    __half lw = __float2half_rn(v.w - __half2float(hw));
    __half2* base = (__half2*)(g_cb2 + (size_t)k * K_STORE + t * 4);
    base[0] = __halves2half2(hx, hy); base[1] = __halves2half2(hz, hw);
    base[128] = __halves2half2(lx, ly); base[129] = __halves2half2(lz, lw);
    float s = v.x * v.x + v.y * v.y + v.z * v.z + v.w * v.w;
    #pragma unroll
    for (int o = 16; o; o >>= 1) s += __shfl_down_sync(0xffffffffu, s, o);
    if ((t & 31) == 0) ssum[t >> 5] = s;
    __syncthreads();
    if (t == 0) g_c2[k] = (k < K_SUB) ? (ssum[0] + ssum[1]) : 3.0e38f;
}

// ---------------- kernel 2: HMMA GEMM + argmin + atomic merge ----------------
// CTA tile 128 tokens x 256 cands, 512 threads (16 warps, 4/SMSP).
// Warp grid 2(m) x 8(n), warp tile 64x32 (same reg pressure as R4).
// Virtual K'=768 in 12 chunks of 64 halves (dedup storage K=512):
//   chunks 0-3: xh.ch, 4-7: xh.cl, 8-11: xl.ch
// 3-stage cp.async ring, ONE __syncthreads per chunk.
#define CHUNK_H 64
#define A_CH (128 * 128)              // 16 KB
#define B_CH (256 * 128)              // 32 KB
#define STAGE (A_CH + B_CH)           // 48 KB
#define DYN_SMEM (3 * STAGE + 1024)   // 148.5 KB (1 CTA/SM)

__global__ void __launch_bounds__(512, 1) k_tc(void) {
    extern __shared__ __align__(16) unsigned char dynraw[];
    char* sb = (char*)(((uintptr_t)dynraw + 1023) & ~(uintptr_t)1023);
    const uint32_t s0 = smem_u32(sb);

    __shared__ float c2s[256];
    __shared__ float sd[128][8];
    __shared__ int   si[128][8];

    const int tid = threadIdx.x;
    const int wid = tid >> 5, lane = tid & 31;
    const int wm = wid & 1, wn = wid >> 1;          // 2 x 8 warp grid
    const int lr = lane & 7, lg = lane >> 3;
    const int tokBase = blockIdx.x * 128;
    const int nBase   = blockIdx.y * 256;

    if (tid < 256) c2s[tid] = g_c2[nBase + tid];

    const __half* Ag = g_xb  + (size_t)tokBase * K_STORE;
    const __half* Bg = g_cb2 + (size_t)nBase * K_STORE;

    float acc[4][4][4];
    #pragma unroll
    for (int a = 0; a < 4; a++)
        #pragma unroll
        for (int b = 0; b < 4; b++)
            #pragma unroll
            for (int e = 0; e < 4; e++) acc[a][b][e] = 0.f;

    int arow[4], brow[2];
    #pragma unroll
    for (int mf = 0; mf < 4; mf++) arow[mf] = wm * 64 + mf * 16 + lr + ((lg & 1) << 3);
    #pragma unroll
    for (int nb = 0; nb < 2; nb++) brow[nb] = wn * 32 + nb * 16 + lr + ((lg >> 1) << 3);
    const int acol = lg >> 1, bcol = lg & 1;

    auto issue = [&](int ch) {
        const uint32_t st = s0 + (ch % 3) * STAGE;
        int aoff = (ch < 8) ? (ch & 3) * CHUNK_H : (256 + (ch & 3) * CHUNK_H);
        int boff = (ch < 4) ? ch * CHUNK_H
                 : (ch < 8) ? (256 + (ch & 3) * CHUNK_H) : (ch & 3) * CHUNK_H;
        #pragma unroll
        for (int q = 0; q < 2; q++) {               // A: 1024 float4 / 512 thr
            int idx = q * 512 + tid;
            int row = idx >> 3, c = idx & 7;
            cpa16(st + row * 128 + ((c ^ (row & 7)) << 4),
                  Ag + (size_t)row * K_STORE + aoff + c * 8);
        }
        #pragma unroll
        for (int q = 0; q < 4; q++) {               // B: 2048 float4 / 512 thr
            int idx = q * 512 + tid;
            int row = idx >> 3, c = idx & 7;
            cpa16(st + A_CH + row * 128 + ((c ^ (row & 7)) << 4),
                  Bg + (size_t)row * K_STORE + boff + c * 8);
        }
        CP_COMMIT();
    };

    issue(0);
    issue(1);
    #pragma unroll 1
    for (int ch = 0; ch < 12; ++ch) {
        if (ch < 11) { CP_WAIT(1); } else { CP_WAIT(0); }
        __syncthreads();                  // chunk ch visible; stage (ch-1)%3 free
        if (ch + 2 < 12) issue(ch + 2);   // writes stage (ch+2)%3 == (ch-1)%3

        const uint32_t sA = s0 + (ch % 3) * STAGE;
        const uint32_t sB = sA + A_CH;
        #pragma unroll
        for (int ks = 0; ks < 4; ++ks) {
            uint32_t af[4][4], bf[2][4];
            #pragma unroll
            for (int mf = 0; mf < 4; mf++) {
                int r = arow[mf], c16 = ks * 2 + acol;
                ldsm4(af[mf], sA + r * 128 + ((c16 ^ (r & 7)) << 4));
            }
            #pragma unroll
            for (int nb = 0; nb < 2; nb++) {
                int r = brow[nb], c16 = ks * 2 + bcol;
                ldsm4(bf[nb], sB + r * 128 + ((c16 ^ (r & 7)) << 4));
            }
            #pragma unroll
            for (int mf = 0; mf < 4; mf++)
                #pragma unroll
                for (int nf = 0; nf < 4; nf++)
                    mma16816(acc[mf][nf], af[mf], bf[nf >> 1][(nf & 1) * 2],
                             bf[nf >> 1][(nf & 1) * 2 + 1]);
        }
    }

    // epilogue: dist = ||c||^2 - 2*dot; thread -> quad -> n-warps -> atomicMin
    #pragma unroll
    for (int mf = 0; mf < 4; mf++) {
        #pragma unroll
        for (int h = 0; h < 2; h++) {
            int rowL = wm * 64 + mf * 16 + (lane >> 2) + h * 8;
            float best = 3.4e38f; int bi = 0x7fffffff;
            #pragma unroll
            for (int nf = 0; nf < 4; nf++)
                #pragma unroll
                for (int j = 0; j < 2; j++) {
                    int colL = wn * 32 + nf * 8 + (lane & 3) * 2 + j;
                    float d = c2s[colL] - 2.0f * acc[mf][nf][h * 2 + j];
                    int cg = nBase + colL;
                    if (d < best || (d == best && cg < bi)) { best = d; bi = cg; }
                }
            #pragma unroll
            for (int o = 1; o <= 2; o <<= 1) {
                float od = __shfl_xor_sync(0xffffffffu, best, o);
                int   oi = __shfl_xor_sync(0xffffffffu, bi, o);
                if (od < best || (od == best && oi < bi)) { best = od; bi = oi; }
            }
            if ((lane & 3) == 0) { sd[rowL][wn] = best; si[rowL][wn] = bi; }
        }
    }
    __syncthreads();
    if (tid < 128) {
        float best = sd[tid][0]; int bi = si[tid][0];
        #pragma unroll
        for (int w = 1; w < 8; w++) {
            float d = sd[tid][w]; int i2 = si[tid][w];
            if (d < best || (d == best && i2 < bi)) { best = d; bi = i2; }
        }
        unsigned long long pk = ((unsigned long long)fmap(best) << 32) | (uint32_t)bi;
        atomicMin(&g_best64[tokBase + tid], pk);
    }
}

// ---------------- kernel 3: resolve packed argmin -> codebook index ----------------
__global__ void k_resolve(const int* __restrict__ rnd, float* __restrict__ out) {
    int t = blockIdx.x * 256 + threadIdx.x;
    int bi = (int)(unsigned)(g_best64[t] & 0xFFFFFFFFull);
    int ci = rnd[bi];
    g_fidx[t] = ci;
    out[OUT_IDX + t] = (float)ci;
}

// ---------------- kernel 4: gather + loss partials ----------------
__global__ void k_gather(const float* __restrict__ x, const float* __restrict__ cb,
                         float* __restrict__ out) {
    __shared__ float red[256];
    int tid = threadIdx.x;
    float s = 0.f;
    #pragma unroll
    for (int j = 0; j < 4; j++) {
        int f = blockIdx.x * 1024 + j * 256 + tid;
        int tok = f >> 6, off = f & 63;
        int ci = g_fidx[tok];
        float4 c = ((const float4*)cb)[(size_t)ci * 64 + off];
        float4 xv = ((const float4*)x)[f];
        ((float4*)out)[f] = c;
        float dx = c.x - xv.x, dy = c.y - xv.y, dz = c.z - xv.z, dw = c.w - xv.w;
        s += dx * dx + dy * dy + dz * dz + dw * dw;
    }
    red[tid] = s;
    __syncthreads();
    for (int o = 128; o; o >>= 1) {
        if (tid < o) red[tid] += red[tid + o];
        __syncthreads();
    }
    if (tid == 0) g_partial[blockIdx.x] = red[0];
}

// ---------------- kernel 5: final loss reduce ----------------
__global__ void k_loss(float* __restrict__ out) {
    __shared__ float red[256];
    int tid = threadIdx.x;
    float s = 0.f;
    for (int j = tid; j < 1024; j += 256) s += g_partial[j];
    red[tid] = s;
    __syncthreads();
    for (int o = 128; o; o >>= 1) {
        if (tid < o) red[tid] += red[tid + o];
        __syncthreads();
    }
    if (tid == 0) out[OUT_LOSS] = red[0] / (float)OUT_TOKENS;
}

// ---------------- launch ----------------
extern "C" void kernel_launch(void* const* d_in, const int* in_sizes, int n_in,
                              void* d_out, int out_size) {
    const float* x   = (const float*)d_in[0];
    const float* cb  = (const float*)d_in[1];
    const int*   rnd = (const int*)d_in[2];
    float* out = (float*)d_out;

    static int smem_set = 0;
    if (!smem_set) {
        cudaFuncSetAttribute(k_tc, cudaFuncAttributeMaxDynamicSharedMemorySize, DYN_SMEM);
        smem_set = 1;
    }

    k_prep_x<<<4096, 256>>>(x);
    k_prep_c<<<K_PAD, 64>>>(cb, rnd);
    k_tc<<<dim3(128, N_YT), 512, DYN_SMEM>>>();
    k_resolve<<<64, 256>>>(rnd, out);
    k_gather<<<1024, 256>>>(x, cb, out);
    k_loss<<<1, 256>>>(out);
}

// round 7
// speedup vs baseline: 1.1320x; 1.1320x over previous
#include <cuda_runtime.h>
#include <cuda_fp16.h>
#include <cstdint>

// ---------------- problem constants ----------------
#define N_TOK   16384          // B*S
#define D_DIM   256
#define K_SUB   3686
#define K_PAD   3840           // 30 * 128
#define N_YT    30             // candidate tiles of 128
#define K_STORE 512            // stored K: [hi|lo]
#define OUT_TOKENS  (N_TOK * D_DIM)
#define OUT_LOSS    OUT_TOKENS
#define OUT_IDX     (OUT_TOKENS + 1)

// ---------------- device scratch ----------------
__device__ __align__(16) __half g_xb[N_TOK * K_STORE];    // [xh|xl] 16.8 MB
__device__ __align__(16) __half g_cb2[K_PAD * K_STORE];   // [ch|cl]  3.9 MB
__device__ float g_c2[K_PAD];
__device__ unsigned long long g_best64[N_TOK];            // packed (dist,idx)
__device__ float g_partial[1024];

// ---------------- PTX helpers ----------------
__device__ __forceinline__ uint32_t smem_u32(const void* p) {
    uint32_t a;
    asm("{ .reg .u64 t; cvta.to.shared.u64 t, %1; cvt.u32.u64 %0, t; }" : "=r"(a) : "l"(p));
    return a;
}
__device__ __forceinline__ void cpa16(uint32_t dst, const void* src) {
    asm volatile("cp.async.cg.shared.global [%0], [%1], 16;" :: "r"(dst), "l"(src));
}
#define CP_COMMIT() asm volatile("cp.async.commit_group;" ::: "memory")
#define CP_WAIT(n)  asm volatile("cp.async.wait_group %0;" :: "n"(n) : "memory")

__device__ __forceinline__ void ldsm4(uint32_t* r, uint32_t a) {
    asm volatile("ldmatrix.sync.aligned.m8n8.x4.shared.b16 {%0,%1,%2,%3}, [%4];"
        : "=r"(r[0]), "=r"(r[1]), "=r"(r[2]), "=r"(r[3]) : "r"(a));
}
__device__ __forceinline__ void mma16816(float* c, const uint32_t* a,
                                         uint32_t b0, uint32_t b1) {
    asm volatile("mma.sync.aligned.m16n8k16.row.col.f32.f16.f16.f32 "
        "{%0,%1,%2,%3}, {%4,%5,%6,%7}, {%8,%9}, {%0,%1,%2,%3};"
        : "+f"(c[0]), "+f"(c[1]), "+f"(c[2]), "+f"(c[3])
        : "r"(a[0]), "r"(a[1]), "r"(a[2]), "r"(a[3]), "r"(b0), "r"(b1));
}

// order-preserving float -> uint32 map
__device__ __forceinline__ uint32_t fmap(float f) {
    uint32_t b = __float_as_uint(f);
    return (b & 0x80000000u) ? ~b : (b | 0x80000000u);
}

// ---------------- kernel 1a: split x -> fp16 hi/lo [xh|xl]; init g_best64 ----
__global__ void k_prep_x(const float* __restrict__ x) {
    int i = blockIdx.x * 256 + threadIdx.x;       // float4 index (1M)
    if (i < N_TOK) g_best64[i] = 0xFFFFFFFFFFFFFFFFull;
    int tok = i >> 6, d4 = i & 63;
    float4 v = ((const float4*)x)[i];
    __half hx = __float2half_rn(v.x), hy = __float2half_rn(v.y);
    __half hz = __float2half_rn(v.z), hw = __float2half_rn(v.w);
    __half lx = __float2half_rn(v.x - __half2float(hx));
    __half ly = __float2half_rn(v.y - __half2float(hy));
    __half lz = __float2half_rn(v.z - __half2float(hz));
    __half lw = __float2half_rn(v.w - __half2float(hw));
    __half2* base = (__half2*)(g_xb + (size_t)tok * K_STORE + d4 * 4);
    base[0] = __halves2half2(hx, hy); base[1] = __halves2half2(hz, hw);
    base[128] = __halves2half2(lx, ly); base[129] = __halves2half2(lz, lw);
}

// ---- kernel 1b: gather sub-codebook, split [ch|cl], row norms ----
__global__ void k_prep_c(const float* __restrict__ cb, const int* __restrict__ rnd) {
    int k = blockIdx.x;          // 0..K_PAD-1
    int t = threadIdx.x;         // 64 threads x float4
    __shared__ float ssum[2];
    float4 v = make_float4(0.f, 0.f, 0.f, 0.f);
    if (k < K_SUB) v = ((const float4*)(cb + (size_t)rnd[k] * D_DIM))[t];
    __half hx = __float2half_rn(v.x), hy = __float2half_rn(v.y);
    __half hz = __float2half_rn(v.z), hw = __float2half_rn(v.w);
    __half lx = __float2half_rn(v.x - __half2float(hx));
    __half ly = __float2half_rn(v.y - __half2float(hy));
    __half lz = __float2half_rn(v.z - __half2float(hz));
    __half lw = __float2half_rn(v.w - __half2float(hw));
    __half2* base = (__half2*)(g_cb2 + (size_t)k * K_STORE + t * 4);
    base[0] = __halves2half2(hx, hy); base[1] = __halves2half2(hz, hw);
    base[128] = __halves2half2(lx, ly); base[129] = __halves2half2(lz, lw);
    float s = v.x * v.x + v.y * v.y + v.z * v.z + v.w * v.w;
    #pragma unroll
    for (int o = 16; o; o >>= 1) s += __shfl_down_sync(0xffffffffu, s, o);
    if ((t & 31) == 0) ssum[t >> 5] = s;
    __syncthreads();
    if (t == 0) g_c2[k] = (k < K_SUB) ? (ssum[0] + ssum[1]) : 3.0e38f;
}

// ---------------- kernel 2: HMMA GEMM + argmin + atomic merge ----------------
// CTA tile 128 tokens x 128 cands, 256 threads, 8 warps 2(m) x 4(n), warp 64x32.
// Virtual K'=768 in 12 chunks of 64 halves (dedup storage K=512):
//   chunks 0-3: xh.ch, 4-7: xh.cl, 8-11: xl.ch
// 3-stage cp.async ring, ONE __syncthreads per chunk, 2 CTAs/SM.
#define CHUNK_H 64
#define A_CH (128 * 128)              // 16 KB
#define B_CH (128 * 128)              // 16 KB
#define STAGE (A_CH + B_CH)           // 32 KB
#define DYN_SMEM (3 * STAGE + 1024)   // 99.3 KB -> 2 CTAs/SM

__global__ void __launch_bounds__(256, 2) k_tc(void) {
    extern __shared__ __align__(16) unsigned char dynraw[];
    char* sb = (char*)(((uintptr_t)dynraw + 1023) & ~(uintptr_t)1023);
    const uint32_t s0 = smem_u32(sb);

    __shared__ float c2s[128];
    __shared__ float sd[128][4];
    __shared__ int   si[128][4];

    const int tid = threadIdx.x;
    const int wid = tid >> 5, lane = tid & 31;
    const int wm = wid & 1, wn = wid >> 1;          // 2 x 4 warp grid
    const int lr = lane & 7, lg = lane >> 3;
    const int tokBase = blockIdx.x * 128;
    const int nBase   = blockIdx.y * 128;

    if (tid < 128) c2s[tid] = g_c2[nBase + tid];

    const __half* Ag = g_xb  + (size_t)tokBase * K_STORE;
    const __half* Bg = g_cb2 + (size_t)nBase * K_STORE;

    float acc[4][4][4];
    #pragma unroll
    for (int a = 0; a < 4; a++)
        #pragma unroll
        for (int b = 0; b < 4; b++)
            #pragma unroll
            for (int e = 0; e < 4; e++) acc[a][b][e] = 0.f;

    int arow[4], brow[2];
    #pragma unroll
    for (int mf = 0; mf < 4; mf++) arow[mf] = wm * 64 + mf * 16 + lr + ((lg & 1) << 3);
    #pragma unroll
    for (int nb = 0; nb < 2; nb++) brow[nb] = wn * 32 + nb * 16 + lr + ((lg >> 1) << 3);
    const int acol = lg >> 1, bcol = lg & 1;

    auto issue = [&](int ch) {
        const uint32_t st = s0 + (ch % 3) * STAGE;
        int aoff = (ch < 8) ? (ch & 3) * CHUNK_H : (256 + (ch & 3) * CHUNK_H);
        int boff = (ch < 4) ? ch * CHUNK_H
                 : (ch < 8) ? (256 + (ch & 3) * CHUNK_H) : (ch & 3) * CHUNK_H;
        #pragma unroll
        for (int q = 0; q < 4; q++) {               // A: 1024 float4
            int idx = q * 256 + tid;
            int row = idx >> 3, c = idx & 7;
            cpa16(st + row * 128 + ((c ^ (row & 7)) << 4),
                  Ag + (size_t)row * K_STORE + aoff + c * 8);
        }
        #pragma unroll
        for (int q = 0; q < 4; q++) {               // B: 1024 float4
            int idx = q * 256 + tid;
            int row = idx >> 3, c = idx & 7;
            cpa16(st + A_CH + row * 128 + ((c ^ (row & 7)) << 4),
                  Bg + (size_t)row * K_STORE + boff + c * 8);
        }
        CP_COMMIT();
    };

    issue(0);
    issue(1);
    #pragma unroll 1
    for (int ch = 0; ch < 12; ++ch) {
        if (ch < 11) { CP_WAIT(1); } else { CP_WAIT(0); }
        __syncthreads();                  // chunk ch visible; stage (ch-1)%3 free
        if (ch + 2 < 12) issue(ch + 2);   // writes stage (ch+2)%3 == (ch-1)%3

        const uint32_t sA = s0 + (ch % 3) * STAGE;
        const uint32_t sB = sA + A_CH;
        #pragma unroll
        for (int ks = 0; ks < 4; ++ks) {
            uint32_t af[4][4], bf[2][4];
            #pragma unroll
            for (int mf = 0; mf < 4; mf++) {
                int r = arow[mf], c16 = ks * 2 + acol;
                ldsm4(af[mf], sA + r * 128 + ((c16 ^ (r & 7)) << 4));
            }
            #pragma unroll
            for (int nb = 0; nb < 2; nb++) {
                int r = brow[nb], c16 = ks * 2 + bcol;
                ldsm4(bf[nb], sB + r * 128 + ((c16 ^ (r & 7)) << 4));
            }
            #pragma unroll
            for (int mf = 0; mf < 4; mf++)
                #pragma unroll
                for (int nf = 0; nf < 4; nf++)
                    mma16816(acc[mf][nf], af[mf], bf[nf >> 1][(nf & 1) * 2],
                             bf[nf >> 1][(nf & 1) * 2 + 1]);
        }
    }

    // epilogue: dist = ||c||^2 - 2*dot; thread -> quad -> n-warps -> atomicMin
    #pragma unroll
    for (int mf = 0; mf < 4; mf++) {
        #pragma unroll
        for (int h = 0; h < 2; h++) {
            int rowL = wm * 64 + mf * 16 + (lane >> 2) + h * 8;
            float best = 3.4e38f; int bi = 0x7fffffff;
            #pragma unroll
            for (int nf = 0; nf < 4; nf++)
                #pragma unroll
                for (int j = 0; j < 2; j++) {
                    int colL = wn * 32 + nf * 8 + (lane & 3) * 2 + j;
                    float d = c2s[colL] - 2.0f * acc[mf][nf][h * 2 + j];
                    int cg = nBase + colL;
                    if (d < best || (d == best && cg < bi)) { best = d; bi = cg; }
                }
            #pragma unroll
            for (int o = 1; o <= 2; o <<= 1) {
                float od = __shfl_xor_sync(0xffffffffu, best, o);
                int   oi = __shfl_xor_sync(0xffffffffu, bi, o);
                if (od < best || (od == best && oi < bi)) { best = od; bi = oi; }
            }
            if ((lane & 3) == 0) { sd[rowL][wn] = best; si[rowL][wn] = bi; }
        }
    }
    __syncthreads();
    if (tid < 128) {
        float best = sd[tid][0]; int bi = si[tid][0];
        #pragma unroll
        for (int w = 1; w < 4; w++) {
            float d = sd[tid][w]; int i2 = si[tid][w];
            if (d < best || (d == best && i2 < bi)) { best = d; bi = i2; }
        }
        unsigned long long pk = ((unsigned long long)fmap(best) << 32) | (uint32_t)bi;
        atomicMin(&g_best64[tokBase + tid], pk);
    }
}

// ---- kernel 3: fused resolve + gather + loss partials ----
__global__ void k_gather(const float* __restrict__ x, const float* __restrict__ cb,
                         const int* __restrict__ rnd, float* __restrict__ out) {
    __shared__ float red[256];
    int tid = threadIdx.x;
    float s = 0.f;
    #pragma unroll
    for (int j = 0; j < 4; j++) {
        int f = blockIdx.x * 1024 + j * 256 + tid;
        int tok = f >> 6, off = f & 63;
        int bi = (int)(unsigned)(g_best64[tok] & 0xFFFFFFFFull);
        int ci = rnd[bi];
        if (off == 0) out[OUT_IDX + tok] = (float)ci;
        float4 c = ((const float4*)cb)[(size_t)ci * 64 + off];
        float4 xv = ((const float4*)x)[f];
        ((float4*)out)[f] = c;
        float dx = c.x - xv.x, dy = c.y - xv.y, dz = c.z - xv.z, dw = c.w - xv.w;
        s += dx * dx + dy * dy + dz * dz + dw * dw;
    }
    red[tid] = s;
    __syncthreads();
    for (int o = 128; o; o >>= 1) {
        if (tid < o) red[tid] += red[tid + o];
        __syncthreads();
    }
    if (tid == 0) g_partial[blockIdx.x] = red[0];
}

// ---------------- kernel 4: final loss reduce ----------------
__global__ void k_loss(float* __restrict__ out) {
    __shared__ float red[256];
    int tid = threadIdx.x;
    float s = 0.f;
    for (int j = tid; j < 1024; j += 256) s += g_partial[j];
    red[tid] = s;
    __syncthreads();
    for (int o = 128; o; o >>= 1) {
        if (tid < o) red[tid] += red[tid + o];
        __syncthreads();
    }
    if (tid == 0) out[OUT_LOSS] = red[0] / (float)OUT_TOKENS;
}

// ---------------- launch ----------------
extern "C" void kernel_launch(void* const* d_in, const int* in_sizes, int n_in,
                              void* d_out, int out_size) {
    const float* x   = (const float*)d_in[0];
    const float* cb  = (const float*)d_in[1];
    const int*   rnd = (const int*)d_in[2];
    float* out = (float*)d_out;

    static int smem_set = 0;
    if (!smem_set) {
        cudaFuncSetAttribute(k_tc, cudaFuncAttributeMaxDynamicSharedMemorySize, DYN_SMEM);
        smem_set = 1;
    }

    k_prep_x<<<4096, 256>>>(x);
    k_prep_c<<<K_PAD, 64>>>(cb, rnd);
    k_tc<<<dim3(128, N_YT), 256, DYN_SMEM>>>();
    k_gather<<<1024, 256>>>(x, cb, rnd, out);
    k_loss<<<1, 256>>>(out);
}

// round 8
// speedup vs baseline: 1.3114x; 1.1585x over previous
#include <cuda_runtime.h>
#include <cuda_fp16.h>
#include <cstdint>

// ---------------- problem constants ----------------
#define N_TOK   16384          // B*S
#define D_DIM   256
#define K_SUB   3686
#define K_PAD   3840           // 30 * 128
#define N_YT    30             // candidate tiles of 128
#define OUT_TOKENS  (N_TOK * D_DIM)
#define OUT_LOSS    OUT_TOKENS
#define OUT_IDX     (OUT_TOKENS + 1)

// ---------------- device scratch ----------------
__device__ __align__(16) __half g_xh[N_TOK * D_DIM];      // x hi fp16   8.4 MB
__device__ __align__(16) __half g_ch[K_PAD * D_DIM];      // c hi fp16   2.0 MB
__device__ __align__(16) __half g_dmat[(size_t)N_TOK * K_PAD];  // d_hh fp16, 126 MB
__device__ float g_c2[K_PAD];
__device__ float g_nxh[N_TOK];                            // ||xh|| per token
__device__ float g_nxl[N_TOK];                            // ||x - xh|| per token
__device__ unsigned g_mcl;                                // max_k ||cl|| (float bits)
__device__ unsigned g_mc;                                 // max_k ||c||  (float bits)
__device__ unsigned long long g_best64[N_TOK];            // packed (fmap(d_hh),idx)
__device__ int   g_fidx[N_TOK];
__device__ float g_partial[1024];

// ---------------- PTX helpers ----------------
__device__ __forceinline__ uint32_t smem_u32(const void* p) {
    uint32_t a;
    asm("{ .reg .u64 t; cvta.to.shared.u64 t, %1; cvt.u32.u64 %0, t; }" : "=r"(a) : "l"(p));
    return a;
}
__device__ __forceinline__ void cpa16(uint32_t dst, const void* src) {
    asm volatile("cp.async.cg.shared.global [%0], [%1], 16;" :: "r"(dst), "l"(src));
}
#define CP_COMMIT() asm volatile("cp.async.commit_group;" ::: "memory")
#define CP_WAIT(n)  asm volatile("cp.async.wait_group %0;" :: "n"(n) : "memory")

__device__ __forceinline__ void ldsm4(uint32_t* r, uint32_t a) {
    asm volatile("ldmatrix.sync.aligned.m8n8.x4.shared.b16 {%0,%1,%2,%3}, [%4];"
        : "=r"(r[0]), "=r"(r[1]), "=r"(r[2]), "=r"(r[3]) : "r"(a));
}
__device__ __forceinline__ void mma16816(float* c, const uint32_t* a,
                                         uint32_t b0, uint32_t b1) {
    asm volatile("mma.sync.aligned.m16n8k16.row.col.f32.f16.f16.f32 "
        "{%0,%1,%2,%3}, {%4,%5,%6,%7}, {%8,%9}, {%0,%1,%2,%3};"
        : "+f"(c[0]), "+f"(c[1]), "+f"(c[2]), "+f"(c[3])
        : "r"(a[0]), "r"(a[1]), "r"(a[2]), "r"(a[3]), "r"(b0), "r"(b1));
}

// order-preserving float -> uint32 map
__device__ __forceinline__ uint32_t fmap(float f) {
    uint32_t b = __float_as_uint(f);
    return (b & 0x80000000u) ? ~b : (b | 0x80000000u);
}
__device__ __forceinline__ float funmap(uint32_t u) {
    return (u & 0x80000000u) ? __uint_as_float(u & 0x7FFFFFFFu)
                             : __uint_as_float(~u);
}

// ---------------- kernel 1a: x -> xh fp16; exact norms; init best64 ----
// 2048 blocks x 256 threads: warp w handles token blockIdx*8 + w.
__global__ void k_prep_x(const float* __restrict__ x) {
    int wid = threadIdx.x >> 5, lane = threadIdx.x & 31;
    int tok = blockIdx.x * 8 + wid;
    const float* xr = x + (size_t)tok * D_DIM + lane * 8;
    float4 a = ((const float4*)xr)[0];
    float4 b = ((const float4*)xr)[1];
    float v[8] = {a.x, a.y, a.z, a.w, b.x, b.y, b.z, b.w};
    __half h[8];
    float sh = 0.f, sl = 0.f;
    #pragma unroll
    for (int i = 0; i < 8; i++) {
        h[i] = __float2half_rn(v[i]);
        float hf = __half2float(h[i]);
        float lf = v[i] - hf;
        sh += hf * hf; sl += lf * lf;
    }
    *(uint4*)(g_xh + (size_t)tok * D_DIM + lane * 8) = *(uint4*)h;
    #pragma unroll
    for (int o = 16; o; o >>= 1) {
        sh += __shfl_xor_sync(0xffffffffu, sh, o);
        sl += __shfl_xor_sync(0xffffffffu, sl, o);
    }
    if (lane == 0) {
        g_nxh[tok] = sqrtf(sh);
        g_nxl[tok] = sqrtf(sl);
        g_best64[tok] = 0xFFFFFFFFFFFFFFFFull;
    }
}

// ---- kernel 1b: gather sub-codebook -> ch fp16; c2; global max norms ----
__global__ void k_prep_c(const float* __restrict__ cb, const int* __restrict__ rnd) {
    int k = blockIdx.x;          // 0..K_PAD-1
    int t = threadIdx.x;         // 64 threads x float4
    __shared__ float s2w[2], slw[2];
    float4 v = make_float4(0.f, 0.f, 0.f, 0.f);
    if (k < K_SUB) v = ((const float4*)(cb + (size_t)rnd[k] * D_DIM))[t];
    __half h[4] = {__float2half_rn(v.x), __float2half_rn(v.y),
                   __float2half_rn(v.z), __float2half_rn(v.w)};
    *(uint2*)(g_ch + (size_t)k * D_DIM + t * 4) = *(uint2*)h;
    float lx = v.x - __half2float(h[0]), ly = v.y - __half2float(h[1]);
    float lz = v.z - __half2float(h[2]), lw = v.w - __half2float(h[3]);
    float s2 = v.x*v.x + v.y*v.y + v.z*v.z + v.w*v.w;
    float sl = lx*lx + ly*ly + lz*lz + lw*lw;
    #pragma unroll
    for (int o = 16; o; o >>= 1) {
        s2 += __shfl_down_sync(0xffffffffu, s2, o);
        sl += __shfl_down_sync(0xffffffffu, sl, o);
    }
    if ((t & 31) == 0) { s2w[t >> 5] = s2; slw[t >> 5] = sl; }
    __syncthreads();
    if (t == 0) {
        float c2 = s2w[0] + s2w[1];
        float cl2 = slw[0] + slw[1];
        g_c2[k] = (k < K_SUB) ? c2 : 3.0e38f;
        if (k < K_SUB) {
            atomicMax(&g_mc,  __float_as_uint(sqrtf(c2)));
            atomicMax(&g_mcl, __float_as_uint(sqrtf(cl2)));
        }
    }
}

// ---------------- kernel 2: fp16 HMMA GEMM (hh term only) ----------------
// 128x128 tile, 256 threads, 8 warps 2(m)x4(n), warp 64x32, K=256 in 4 chunks.
// Stores d_hh fp16 matrix + per-token packed atomicMin.
#define CHUNK_H 64
#define A_CH (128 * 128)              // 16 KB
#define B_CH (128 * 128)              // 16 KB
#define STAGE (A_CH + B_CH)           // 32 KB
#define DYN_SMEM (3 * STAGE + 1024)

__global__ void __launch_bounds__(256, 2) k_tc(void) {
    extern __shared__ __align__(16) unsigned char dynraw[];
    char* sb = (char*)(((uintptr_t)dynraw + 1023) & ~(uintptr_t)1023);
    const uint32_t s0 = smem_u32(sb);

    __shared__ float c2s[128];
    __shared__ float sd[128][4];
    __shared__ int   si[128][4];

    const int tid = threadIdx.x;
    const int wid = tid >> 5, lane = tid & 31;
    const int wm = wid & 1, wn = wid >> 1;
    const int lr = lane & 7, lg = lane >> 3;
    const int tokBase = blockIdx.x * 128;
    const int nBase   = blockIdx.y * 128;

    if (tid < 128) c2s[tid] = g_c2[nBase + tid];

    const __half* Ag = g_xh + (size_t)tokBase * D_DIM;
    const __half* Bg = g_ch + (size_t)nBase * D_DIM;

    float acc[4][4][4];
    #pragma unroll
    for (int a = 0; a < 4; a++)
        #pragma unroll
        for (int b = 0; b < 4; b++)
            #pragma unroll
            for (int e = 0; e < 4; e++) acc[a][b][e] = 0.f;

    int arow[4], brow[2];
    #pragma unroll
    for (int mf = 0; mf < 4; mf++) arow[mf] = wm * 64 + mf * 16 + lr + ((lg & 1) << 3);
    #pragma unroll
    for (int nb = 0; nb < 2; nb++) brow[nb] = wn * 32 + nb * 16 + lr + ((lg >> 1) << 3);
    const int acol = lg >> 1, bcol = lg & 1;

    auto issue = [&](int ch) {
        const uint32_t st = s0 + (ch % 3) * STAGE;
        #pragma unroll
        for (int q = 0; q < 4; q++) {
            int idx = q * 256 + tid;
            int row = idx >> 3, c = idx & 7;
            cpa16(st + row * 128 + ((c ^ (row & 7)) << 4),
                  Ag + (size_t)row * D_DIM + ch * CHUNK_H + c * 8);
        }
        #pragma unroll
        for (int q = 0; q < 4; q++) {
            int idx = q * 256 + tid;
            int row = idx >> 3, c = idx & 7;
            cpa16(st + A_CH + row * 128 + ((c ^ (row & 7)) << 4),
                  Bg + (size_t)row * D_DIM + ch * CHUNK_H + c * 8);
        }
        CP_COMMIT();
    };

    issue(0);
    issue(1);
    #pragma unroll 1
    for (int ch = 0; ch < 4; ++ch) {
        if (ch < 3) { CP_WAIT(1); } else { CP_WAIT(0); }
        __syncthreads();
        if (ch + 2 < 4) issue(ch + 2);

        const uint32_t sA = s0 + (ch % 3) * STAGE;
        const uint32_t sB = sA + A_CH;
        #pragma unroll
        for (int ks = 0; ks < 4; ++ks) {
            uint32_t af[4][4], bf[2][4];
            #pragma unroll
            for (int mf = 0; mf < 4; mf++) {
                int r = arow[mf], c16 = ks * 2 + acol;
                ldsm4(af[mf], sA + r * 128 + ((c16 ^ (r & 7)) << 4));
            }
            #pragma unroll
            for (int nb = 0; nb < 2; nb++) {
                int r = brow[nb], c16 = ks * 2 + bcol;
                ldsm4(bf[nb], sB + r * 128 + ((c16 ^ (r & 7)) << 4));
            }
            #pragma unroll
            for (int mf = 0; mf < 4; mf++)
                #pragma unroll
                for (int nf = 0; nf < 4; nf++)
                    mma16816(acc[mf][nf], af[mf], bf[nf >> 1][(nf & 1) * 2],
                             bf[nf >> 1][(nf & 1) * 2 + 1]);
        }
    }

    __syncthreads();                         // stages dead; reuse stage0 for d tile
    __half2* dstage = (__half2*)sb;          // 128 x 64 half2 = 32 KB

    // epilogue: d_hh = ||c||^2 - 2*dot; stage fp16 tile + local argmin
    #pragma unroll
    for (int mf = 0; mf < 4; mf++) {
        #pragma unroll
        for (int h = 0; h < 2; h++) {
            int rowL = wm * 64 + mf * 16 + (lane >> 2) + h * 8;
            float best = 3.4e38f; int bi = 0x7fffffff;
            #pragma unroll
            for (int nf = 0; nf < 4; nf++) {
                int colL = wn * 32 + nf * 8 + (lane & 3) * 2;
                float d0 = c2s[colL]     - 2.0f * acc[mf][nf][h * 2];
                float d1 = c2s[colL + 1] - 2.0f * acc[mf][nf][h * 2 + 1];
                dstage[rowL * 64 + (colL >> 1)] = __floats2half2_rn(d0, d1);
                int cg = nBase + colL;
                if (d0 < best || (d0 == best && cg < bi))     { best = d0; bi = cg; }
                if (d1 < best || (d1 == best && cg + 1 < bi)) { best = d1; bi = cg + 1; }
            }
            #pragma unroll
            for (int o = 1; o <= 2; o <<= 1) {
                float od = __shfl_xor_sync(0xffffffffu, best, o);
                int   oi = __shfl_xor_sync(0xffffffffu, bi, o);
                if (od < best || (od == best && oi < bi)) { best = od; bi = oi; }
            }
            if ((lane & 3) == 0) { sd[rowL][wn] = best; si[rowL][wn] = bi; }
        }
    }
    __syncthreads();

    // coalesced d tile store: 2048 uint4, 8 per thread
    #pragma unroll
    for (int q = 0; q < 8; q++) {
        int idx = q * 256 + tid;
        int row = idx >> 4, c16 = idx & 15;
        *(uint4*)(g_dmat + (size_t)(tokBase + row) * K_PAD + nBase + c16 * 8) =
            ((const uint4*)dstage)[idx];
    }

    if (tid < 128) {
        float best = sd[tid][0]; int bi = si[tid][0];
        #pragma unroll
        for (int w = 1; w < 4; w++) {
            float d = sd[tid][w]; int i2 = si[tid][w];
            if (d < best || (d == best && i2 < bi)) { best = d; bi = i2; }
        }
        unsigned long long pk = ((unsigned long long)fmap(best) << 32) | (uint32_t)bi;
        atomicMin(&g_best64[tokBase + tid], pk);
    }
}

// ---------------- kernel 3: margin rescue -> exact argmin ----------------
// 2048 blocks x 256: warp w handles token blockIdx*8 + w.
__global__ void k_rescue(const float* __restrict__ x, const float* __restrict__ cb,
                         const int* __restrict__ rnd, float* __restrict__ out) {
    int wid = threadIdx.x >> 5, lane = threadIdx.x & 31;
    int tok = blockIdx.x * 8 + wid;

    unsigned long long pk = g_best64[tok];
    float dmin = funmap((uint32_t)(pk >> 32));
    float MCL = __uint_as_float(g_mcl), MC = __uint_as_float(g_mc);
    float thr = dmin + 2.0f * (g_nxh[tok] * MCL + g_nxl[tok] * MC) + 0.25f;

    // cache x row: 8 floats per lane
    const float* xr = x + (size_t)tok * D_DIM + lane * 8;
    float4 xa = ((const float4*)xr)[0];
    float4 xb = ((const float4*)xr)[1];

    float best = 3.4e38f; int bi = 0x7fffffff;
    const __half* drow = g_dmat + (size_t)tok * K_PAD;

    #pragma unroll 1
    for (int it = 0; it < K_PAD / 64; ++it) {           // 60 iters, half2/lane
        int k2 = it * 64 + lane * 2;
        __half2 dh = *(const __half2*)(drow + k2);
        float f0 = __low2float(dh), f1 = __high2float(dh);
        unsigned b0 = __ballot_sync(0xffffffffu, f0 <= thr);
        unsigned b1 = __ballot_sync(0xffffffffu, f1 <= thr);
        #pragma unroll 1
        for (int half = 0; half < 2; ++half) {
            unsigned bb = half ? b1 : b0;
            while (bb) {
                int src = __ffs(bb) - 1; bb &= bb - 1;
                int kk = it * 64 + src * 2 + half;
                int ci = rnd[kk];                        // kk < K_SUB (pad d = inf)
                const float* cr = cb + (size_t)ci * D_DIM + lane * 8;
                float4 ca = ((const float4*)cr)[0];
                float4 cbv = ((const float4*)cr)[1];
                float p = xa.x*ca.x + xa.y*ca.y + xa.z*ca.z + xa.w*ca.w
                        + xb.x*cbv.x + xb.y*cbv.y + xb.z*cbv.z + xb.w*cbv.w;
                #pragma unroll
                for (int o = 16; o; o >>= 1) p += __shfl_xor_sync(0xffffffffu, p, o);
                float dex = g_c2[kk] - 2.0f * p;
                if (dex < best || (dex == best && kk < bi)) { best = dex; bi = kk; }
            }
        }
    }
    if (lane == 0) {
        int ci = rnd[bi];
        g_fidx[tok] = ci;
        out[OUT_IDX + tok] = (float)ci;
    }
}

// ---------------- kernel 4: gather + loss partials ----------------
__global__ void k_gather(const float* __restrict__ x, const float* __restrict__ cb,
                         float* __restrict__ out) {
    __shared__ float red[256];
    int tid = threadIdx.x;
    float s = 0.f;
    #pragma unroll
    for (int j = 0; j < 4; j++) {
        int f = blockIdx.x * 1024 + j * 256 + tid;
        int tok = f >> 6, off = f & 63;
        int ci = g_fidx[tok];
        float4 c = ((const float4*)cb)[(size_t)ci * 64 + off];
        float4 xv = ((const float4*)x)[f];
        ((float4*)out)[f] = c;
        float dx = c.x - xv.x, dy = c.y - xv.y, dz = c.z - xv.z, dw = c.w - xv.w;
        s += dx * dx + dy * dy + dz * dz + dw * dw;
    }
    red[tid] = s;
    __syncthreads();
    for (int o = 128; o; o >>= 1) {
        if (tid < o) red[tid] += red[tid + o];
        __syncthreads();
    }
    if (tid == 0) g_partial[blockIdx.x] = red[0];
}

// ---------------- kernel 5: final loss reduce ----------------
__global__ void k_loss(float* __restrict__ out) {
    __shared__ float red[256];
    int tid = threadIdx.x;
    float s = 0.f;
    for (int j = tid; j < 1024; j += 256) s += g_partial[j];
    red[tid] = s;
    __syncthreads();
    for (int o = 128; o; o >>= 1) {
        if (tid < o) red[tid] += red[tid + o];
        __syncthreads();
    }
    if (tid == 0) out[OUT_LOSS] = red[0] / (float)OUT_TOKENS;
}

// ---------------- launch ----------------
extern "C" void kernel_launch(void* const* d_in, const int* in_sizes, int n_in,
                              void* d_out, int out_size) {
    const float* x   = (const float*)d_in[0];
    const float* cb  = (const float*)d_in[1];
    const int*   rnd = (const int*)d_in[2];
    float* out = (float*)d_out;

    static int smem_set = 0;
    if (!smem_set) {
        cudaFuncSetAttribute(k_tc, cudaFuncAttributeMaxDynamicSharedMemorySize, DYN_SMEM);
        smem_set = 1;
    }

    k_prep_x<<<2048, 256>>>(x);
    k_prep_c<<<K_PAD, 64>>>(cb, rnd);
    k_tc<<<dim3(128, N_YT), 256, DYN_SMEM>>>();
    k_rescue<<<2048, 256>>>(x, cb, rnd, out);
    k_gather<<<1024, 256>>>(x, cb, out);
    k_loss<<<1, 256>>>(out);
}

// round 9
// speedup vs baseline: 1.9435x; 1.4820x over previous
#include <cuda_runtime.h>
#include <cuda_fp16.h>
#include <cstdint>

// ---------------- problem constants ----------------
#define N_TOK   16384          // B*S
#define D_DIM   256
#define K_SUB   3686
#define K_PAD   3840           // 30 * 128
#define N_YT    30             // candidate tiles of 128
#define OUT_TOKENS  (N_TOK * D_DIM)
#define OUT_LOSS    OUT_TOKENS
#define OUT_IDX     (OUT_TOKENS + 1)

// ---------------- device scratch ----------------
__device__ __align__(16) __half g_xh[N_TOK * D_DIM];      // x hi fp16   8.4 MB
__device__ __align__(16) __half g_ch[K_PAD * D_DIM];      // c hi fp16   2.0 MB
__device__ __align__(16) __half g_dmat[(size_t)N_TOK * K_PAD];  // d_hh fp16, 126 MB
__device__ float g_tmin[N_TOK * 32];                      // per-(token,tile) min, 2 MB
__device__ float g_c2[K_PAD];
__device__ float g_nxh[N_TOK];                            // ||xh|| per token
__device__ float g_nxl[N_TOK];                            // ||x - xh|| per token
__device__ unsigned g_mcl;                                // max_k ||cl|| (float bits)
__device__ unsigned g_mc;                                 // max_k ||c||  (float bits)
__device__ int   g_fidx[N_TOK];
__device__ float g_partial[1024];

// ---------------- PTX helpers ----------------
__device__ __forceinline__ uint32_t smem_u32(const void* p) {
    uint32_t a;
    asm("{ .reg .u64 t; cvta.to.shared.u64 t, %1; cvt.u32.u64 %0, t; }" : "=r"(a) : "l"(p));
    return a;
}
__device__ __forceinline__ void cpa16(uint32_t dst, const void* src) {
    asm volatile("cp.async.cg.shared.global [%0], [%1], 16;" :: "r"(dst), "l"(src));
}
#define CP_COMMIT() asm volatile("cp.async.commit_group;" ::: "memory")
#define CP_WAIT(n)  asm volatile("cp.async.wait_group %0;" :: "n"(n) : "memory")

__device__ __forceinline__ void ldsm4(uint32_t* r, uint32_t a) {
    asm volatile("ldmatrix.sync.aligned.m8n8.x4.shared.b16 {%0,%1,%2,%3}, [%4];"
        : "=r"(r[0]), "=r"(r[1]), "=r"(r[2]), "=r"(r[3]) : "r"(a));
}
__device__ __forceinline__ void mma16816(float* c, const uint32_t* a,
                                         uint32_t b0, uint32_t b1) {
    asm volatile("mma.sync.aligned.m16n8k16.row.col.f32.f16.f16.f32 "
        "{%0,%1,%2,%3}, {%4,%5,%6,%7}, {%8,%9}, {%0,%1,%2,%3};"
        : "+f"(c[0]), "+f"(c[1]), "+f"(c[2]), "+f"(c[3])
        : "r"(a[0]), "r"(a[1]), "r"(a[2]), "r"(a[3]), "r"(b0), "r"(b1));
}

// ---------------- kernel 1a: x -> xh fp16; exact norms ----
__global__ void k_prep_x(const float* __restrict__ x) {
    int wid = threadIdx.x >> 5, lane = threadIdx.x & 31;
    int tok = blockIdx.x * 8 + wid;
    const float* xr = x + (size_t)tok * D_DIM + lane * 8;
    float4 a = ((const float4*)xr)[0];
    float4 b = ((const float4*)xr)[1];
    float v[8] = {a.x, a.y, a.z, a.w, b.x, b.y, b.z, b.w};
    __half h[8];
    float sh = 0.f, sl = 0.f;
    #pragma unroll
    for (int i = 0; i < 8; i++) {
        h[i] = __float2half_rn(v[i]);
        float hf = __half2float(h[i]);
        float lf = v[i] - hf;
        sh += hf * hf; sl += lf * lf;
    }
    *(uint4*)(g_xh + (size_t)tok * D_DIM + lane * 8) = *(uint4*)h;
    #pragma unroll
    for (int o = 16; o; o >>= 1) {
        sh += __shfl_xor_sync(0xffffffffu, sh, o);
        sl += __shfl_xor_sync(0xffffffffu, sl, o);
    }
    if (lane == 0) {
        g_nxh[tok] = sqrtf(sh);
        g_nxl[tok] = sqrtf(sl);
    }
}

// ---- kernel 1b: gather sub-codebook -> ch fp16; c2; global max norms ----
__global__ void k_prep_c(const float* __restrict__ cb, const int* __restrict__ rnd) {
    int k = blockIdx.x;          // 0..K_PAD-1
    int t = threadIdx.x;         // 64 threads x float4
    __shared__ float s2w[2], slw[2];
    float4 v = make_float4(0.f, 0.f, 0.f, 0.f);
    if (k < K_SUB) v = ((const float4*)(cb + (size_t)rnd[k] * D_DIM))[t];
    __half h[4] = {__float2half_rn(v.x), __float2half_rn(v.y),
                   __float2half_rn(v.z), __float2half_rn(v.w)};
    *(uint2*)(g_ch + (size_t)k * D_DIM + t * 4) = *(uint2*)h;
    float lx = v.x - __half2float(h[0]), ly = v.y - __half2float(h[1]);
    float lz = v.z - __half2float(h[2]), lw = v.w - __half2float(h[3]);
    float s2 = v.x*v.x + v.y*v.y + v.z*v.z + v.w*v.w;
    float sl = lx*lx + ly*ly + lz*lz + lw*lw;
    #pragma unroll
    for (int o = 16; o; o >>= 1) {
        s2 += __shfl_down_sync(0xffffffffu, s2, o);
        sl += __shfl_down_sync(0xffffffffu, sl, o);
    }
    if ((t & 31) == 0) { s2w[t >> 5] = s2; slw[t >> 5] = sl; }
    __syncthreads();
    if (t == 0) {
        float c2 = s2w[0] + s2w[1];
        float cl2 = slw[0] + slw[1];
        g_c2[k] = (k < K_SUB) ? c2 : 3.0e38f;
        if (k < K_SUB) {
            atomicMax(&g_mc,  __float_as_uint(sqrtf(c2)));
            atomicMax(&g_mcl, __float_as_uint(sqrtf(cl2)));
        }
    }
}

// ---------------- kernel 2: fp16 HMMA GEMM (hh term only) ----------------
// 128x128 tile, 256 threads, 8 warps 2(m)x4(n), warp 64x32, K=256 in 4 chunks.
// Stores d_hh fp16 matrix + per-(token,tile) min.
#define CHUNK_H 64
#define A_CH (128 * 128)              // 16 KB
#define B_CH (128 * 128)              // 16 KB
#define STAGE (A_CH + B_CH)           // 32 KB
#define DYN_SMEM (3 * STAGE + 1024)

__global__ void __launch_bounds__(256, 2) k_tc(void) {
    extern __shared__ __align__(16) unsigned char dynraw[];
    char* sb = (char*)(((uintptr_t)dynraw + 1023) & ~(uintptr_t)1023);
    const uint32_t s0 = smem_u32(sb);

    __shared__ float c2s[128];
    __shared__ float sd[128][4];

    const int tid = threadIdx.x;
    const int wid = tid >> 5, lane = tid & 31;
    const int wm = wid & 1, wn = wid >> 1;
    const int lr = lane & 7, lg = lane >> 3;
    const int tokBase = blockIdx.x * 128;
    const int nBase   = blockIdx.y * 128;

    if (tid < 128) c2s[tid] = g_c2[nBase + tid];

    const __half* Ag = g_xh + (size_t)tokBase * D_DIM;
    const __half* Bg = g_ch + (size_t)nBase * D_DIM;

    float acc[4][4][4];
    #pragma unroll
    for (int a = 0; a < 4; a++)
        #pragma unroll
        for (int b = 0; b < 4; b++)
            #pragma unroll
            for (int e = 0; e < 4; e++) acc[a][b][e] = 0.f;

    int arow[4], brow[2];
    #pragma unroll
    for (int mf = 0; mf < 4; mf++) arow[mf] = wm * 64 + mf * 16 + lr + ((lg & 1) << 3);
    #pragma unroll
    for (int nb = 0; nb < 2; nb++) brow[nb] = wn * 32 + nb * 16 + lr + ((lg >> 1) << 3);
    const int acol = lg >> 1, bcol = lg & 1;

    auto issue = [&](int ch) {
        const uint32_t st = s0 + (ch % 3) * STAGE;
        #pragma unroll
        for (int q = 0; q < 4; q++) {
            int idx = q * 256 + tid;
            int row = idx >> 3, c = idx & 7;
            cpa16(st + row * 128 + ((c ^ (row & 7)) << 4),
                  Ag + (size_t)row * D_DIM + ch * CHUNK_H + c * 8);
        }
        #pragma unroll
        for (int q = 0; q < 4; q++) {
            int idx = q * 256 + tid;
            int row = idx >> 3, c = idx & 7;
            cpa16(st + A_CH + row * 128 + ((c ^ (row & 7)) << 4),
                  Bg + (size_t)row * D_DIM + ch * CHUNK_H + c * 8);
        }
        CP_COMMIT();
    };

    issue(0);
    issue(1);
    #pragma unroll 1
    for (int ch = 0; ch < 4; ++ch) {
        if (ch < 3) { CP_WAIT(1); } else { CP_WAIT(0); }
        __syncthreads();
        if (ch + 2 < 4) issue(ch + 2);

        const uint32_t sA = s0 + (ch % 3) * STAGE;
        const uint32_t sB = sA + A_CH;
        #pragma unroll
        for (int ks = 0; ks < 4; ++ks) {
            uint32_t af[4][4], bf[2][4];
            #pragma unroll
            for (int mf = 0; mf < 4; mf++) {
                int r = arow[mf], c16 = ks * 2 + acol;
                ldsm4(af[mf], sA + r * 128 + ((c16 ^ (r & 7)) << 4));
            }
            #pragma unroll
            for (int nb = 0; nb < 2; nb++) {
                int r = brow[nb], c16 = ks * 2 + bcol;
                ldsm4(bf[nb], sB + r * 128 + ((c16 ^ (r & 7)) << 4));
            }
            #pragma unroll
            for (int mf = 0; mf < 4; mf++)
                #pragma unroll
                for (int nf = 0; nf < 4; nf++)
                    mma16816(acc[mf][nf], af[mf], bf[nf >> 1][(nf & 1) * 2],
                             bf[nf >> 1][(nf & 1) * 2 + 1]);
        }
    }

    __syncthreads();                         // stages dead; reuse stage0 for d tile
    __half2* dstage = (__half2*)sb;          // 128 x 64 half2 = 32 KB

    // epilogue: d_hh = ||c||^2 - 2*dot; stage fp16 tile + per-token local min
    #pragma unroll
    for (int mf = 0; mf < 4; mf++) {
        #pragma unroll
        for (int h = 0; h < 2; h++) {
            int rowL = wm * 64 + mf * 16 + (lane >> 2) + h * 8;
            float best = 3.4e38f;
            #pragma unroll
            for (int nf = 0; nf < 4; nf++) {
                int colL = wn * 32 + nf * 8 + (lane & 3) * 2;
                float d0 = c2s[colL]     - 2.0f * acc[mf][nf][h * 2];
                float d1 = c2s[colL + 1] - 2.0f * acc[mf][nf][h * 2 + 1];
                dstage[rowL * 64 + (colL >> 1)] = __floats2half2_rn(d0, d1);
                best = fminf(best, fminf(d0, d1));
            }
            #pragma unroll
            for (int o = 1; o <= 2; o <<= 1)
                best = fminf(best, __shfl_xor_sync(0xffffffffu, best, o));
            if ((lane & 3) == 0) sd[rowL][wn] = best;
        }
    }
    __syncthreads();

    // coalesced d tile store: 2048 uint4, 8 per thread
    #pragma unroll
    for (int q = 0; q < 8; q++) {
        int idx = q * 256 + tid;
        int row = idx >> 4, c16 = idx & 15;
        *(uint4*)(g_dmat + (size_t)(tokBase + row) * K_PAD + nBase + c16 * 8) =
            ((const uint4*)dstage)[idx];
    }

    if (tid < 128) {
        float best = fminf(fminf(sd[tid][0], sd[tid][1]),
                           fminf(sd[tid][2], sd[tid][3]));
        g_tmin[(tokBase + tid) * 32 + blockIdx.y] = best;
    }
}

// ---------------- kernel 3: hierarchical rescue -> exact argmin ----------------
// warp per token; read 30 tile-mins, filter tiles, read only passing d rows.
__global__ void k_rescue(const float* __restrict__ x, const float* __restrict__ cb,
                         const int* __restrict__ rnd, float* __restrict__ out) {
    int wid = threadIdx.x >> 5, lane = threadIdx.x & 31;
    int tok = blockIdx.x * 8 + wid;

    float tm = (lane < N_YT) ? g_tmin[tok * 32 + lane] : 3.4e38f;
    float dmin = tm;
    #pragma unroll
    for (int o = 16; o; o >>= 1)
        dmin = fminf(dmin, __shfl_xor_sync(0xffffffffu, dmin, o));

    float MCL = __uint_as_float(g_mcl), MC = __uint_as_float(g_mc);
    float B = 2.0f * (g_nxh[tok] * MCL + g_nxl[tok] * MC);
    float thr = dmin + 2.0f * B + 0.25f;          // 2B bound + fp16 storage slack

    unsigned tmask = __ballot_sync(0xffffffffu, tm <= thr);

    // cache x row: 8 floats per lane
    const float* xr = x + (size_t)tok * D_DIM + lane * 8;
    float4 xa = ((const float4*)xr)[0];
    float4 xb = ((const float4*)xr)[1];

    float best = 3.4e38f; int bi = 0x7fffffff;
    const __half* drow = g_dmat + (size_t)tok * K_PAD;

    while (tmask) {
        int t = __ffs(tmask) - 1; tmask &= tmask - 1;
        uint2 raw = ((const uint2*)(drow + t * 128))[lane];   // 4 halves/lane
        __half2 h0 = *(__half2*)&raw.x, h1 = *(__half2*)&raw.y;
        float f[4] = {__low2float(h0), __high2float(h0),
                      __low2float(h1), __high2float(h1)};
        #pragma unroll
        for (int j = 0; j < 4; j++) {
            unsigned bb = __ballot_sync(0xffffffffu, f[j] <= thr);
            while (bb) {
                int src = __ffs(bb) - 1; bb &= bb - 1;
                int kk = t * 128 + src * 4 + j;
                int ci = rnd[kk];                 // kk < K_SUB (pad rows are +inf)
                const float* cr = cb + (size_t)ci * D_DIM + lane * 8;
                float4 ca = ((const float4*)cr)[0];
                float4 cbv = ((const float4*)cr)[1];
                float p = xa.x*ca.x + xa.y*ca.y + xa.z*ca.z + xa.w*ca.w
                        + xb.x*cbv.x + xb.y*cbv.y + xb.z*cbv.z + xb.w*cbv.w;
                #pragma unroll
                for (int o = 16; o; o >>= 1) p += __shfl_xor_sync(0xffffffffu, p, o);
                float dex = g_c2[kk] - 2.0f * p;
                if (dex < best || (dex == best && kk < bi)) { best = dex; bi = kk; }
            }
        }
    }
    if (lane == 0) {
        int ci = rnd[bi];
        g_fidx[tok] = ci;
        out[OUT_IDX + tok] = (float)ci;
    }
}

// ---------------- kernel 4: gather + loss partials ----------------
__global__ void k_gather(const float* __restrict__ x, const float* __restrict__ cb,
                         float* __restrict__ out) {
    __shared__ float red[256];
    int tid = threadIdx.x;
    float s = 0.f;
    #pragma unroll
    for (int j = 0; j < 4; j++) {
        int f = blockIdx.x * 1024 + j * 256 + tid;
        int tok = f >> 6, off = f & 63;
        int ci = g_fidx[tok];
        float4 c = ((const float4*)cb)[(size_t)ci * 64 + off];
        float4 xv = ((const float4*)x)[f];
        ((float4*)out)[f] = c;
        float dx = c.x - xv.x, dy = c.y - xv.y, dz = c.z - xv.z, dw = c.w - xv.w;
        s += dx * dx + dy * dy + dz * dz + dw * dw;
    }
    red[tid] = s;
    __syncthreads();
    for (int o = 128; o; o >>= 1) {
        if (tid < o) red[tid] += red[tid + o];
        __syncthreads();
    }
    if (tid == 0) g_partial[blockIdx.x] = red[0];
}

// ---------------- kernel 5: final loss reduce ----------------
__global__ void k_loss(float* __restrict__ out) {
    __shared__ float red[256];
    int tid = threadIdx.x;
    float s = 0.f;
    for (int j = tid; j < 1024; j += 256) s += g_partial[j];
    red[tid] = s;
    __syncthreads();
    for (int o = 128; o; o >>= 1) {
        if (tid < o) red[tid] += red[tid + o];
        __syncthreads();
    }
    if (tid == 0) out[OUT_LOSS] = red[0] / (float)OUT_TOKENS;
}

// ---------------- launch ----------------
extern "C" void kernel_launch(void* const* d_in, const int* in_sizes, int n_in,
                              void* d_out, int out_size) {
    const float* x   = (const float*)d_in[0];
    const float* cb  = (const float*)d_in[1];
    const int*   rnd = (const int*)d_in[2];
    float* out = (float*)d_out;

    static int smem_set = 0;
    if (!smem_set) {
        cudaFuncSetAttribute(k_tc, cudaFuncAttributeMaxDynamicSharedMemorySize, DYN_SMEM);
        smem_set = 1;
    }

    k_prep_x<<<2048, 256>>>(x);
    k_prep_c<<<K_PAD, 64>>>(cb, rnd);
    k_tc<<<dim3(128, N_YT), 256, DYN_SMEM>>>();
    k_rescue<<<2048, 256>>>(x, cb, rnd, out);
    k_gather<<<1024, 256>>>(x, cb, out);
    k_loss<<<1, 256>>>(out);
}